// round 14
// baseline (speedup 1.0000x reference)
#include <cuda_runtime.h>
#include <cstdint>
#include <cstddef>

using u64 = unsigned long long;

// Problem constants
constexpr int B_ = 64;
constexpr int L_ = 512;
constexpr int E_ = 512;
constexpr int G_ = 1536;          // 3*H
constexpr int M_ = B_ * L_;       // 32768 rows per direction
constexpr float LN_EPS = 1e-5f;

// Scratch (device globals: allocation-free)
__device__ float g_px[2ull * 32768ull * 1536ull];   // LN3(x @ Wx) per dir
__device__ float g_ph[2 * 64 * 1536];               // per-step h @ Wh
__device__ float g_hT[2 * 512 * 64];                // hidden transposed [dir][k][b]
__device__ unsigned g_cnt2[2];                      // per-dir grid barrier
__device__ unsigned g_gen2[2];

// ---------------- packed f32x2 / fast-math helpers ----------------
__device__ __forceinline__ u64 pack2(float x, float y) {
    u64 r; asm("mov.b64 %0,{%1,%2};" : "=l"(r) : "f"(x), "f"(y)); return r;
}
__device__ __forceinline__ void fma2(u64& d, u64 a, u64 b) {
    asm("fma.rn.f32x2 %0,%1,%2,%0;" : "+l"(d) : "l"(a), "l"(b));
}
__device__ __forceinline__ u64 add2(u64 a, u64 b) {
    u64 d; asm("add.rn.f32x2 %0,%1,%2;" : "=l"(d) : "l"(a), "l"(b)); return d;
}
__device__ __forceinline__ float tanh_fast(float x) {
    float y; asm("tanh.approx.f32 %0,%1;" : "=f"(y) : "f"(x)); return y;
}
__device__ __forceinline__ float sig_fast(float x) {
    return 0.5f + 0.5f * tanh_fast(0.5f * x);
}

// ---------------------------------------------------------------------------
// Kernel 1: px = xs @ Wx.  BM=128, BN=128, BK=16, 256 threads. (proven)
// ---------------------------------------------------------------------------
__global__ __launch_bounds__(256, 2) void gemm_px_kernel(
    const float* __restrict__ xs,
    const float* __restrict__ Wxf,
    const float* __restrict__ Wxb)
{
    constexpr int BK = 16, LDA = 132;
    __shared__ float As[BK * LDA];     // A transposed [k][m]
    __shared__ float Bs[BK * 128];     // B [k][n]

    const int dir = blockIdx.z;
    const float* W = dir ? Wxb : Wxf;
    const int m0 = blockIdx.y * 128;
    const int n0 = blockIdx.x * 128;
    const int t  = threadIdx.x;
    const int tx = t & 15;
    const int ty = t >> 4;

    const float* apx[2];
    int arow[2], ac4[2];
    const float* bpx[2];
    int brow[2], bc4[2];
#pragma unroll
    for (int i = 0; i < 2; i++) {
        int idx = t + 256 * i;
        arow[i] = idx >> 2;
        ac4[i]  = idx & 3;
        int m   = m0 + arow[i];
        int b   = m >> 9;
        int s   = m & 511;
        int torig = dir ? (511 - s) : s;
        apx[i] = xs + ((size_t)(b * 512 + torig)) * 512 + ac4[i] * 4;
        brow[i] = idx >> 5;
        bc4[i]  = idx & 31;
        bpx[i]  = W + (size_t)brow[i] * G_ + n0 + bc4[i] * 4;
    }

    u64 acc[8][4];
#pragma unroll
    for (int m = 0; m < 8; m++)
#pragma unroll
        for (int np = 0; np < 4; np++) acc[m][np] = 0ull;

    float4 rA[2], rB[2];
#pragma unroll
    for (int i = 0; i < 2; i++) {
        rA[i] = *reinterpret_cast<const float4*>(apx[i]);
        rB[i] = *reinterpret_cast<const float4*>(bpx[i]);
    }

    for (int kt = 0; kt < E_; kt += BK) {
#pragma unroll
        for (int i = 0; i < 2; i++) {
            As[(ac4[i] * 4 + 0) * LDA + arow[i]] = rA[i].x;
            As[(ac4[i] * 4 + 1) * LDA + arow[i]] = rA[i].y;
            As[(ac4[i] * 4 + 2) * LDA + arow[i]] = rA[i].z;
            As[(ac4[i] * 4 + 3) * LDA + arow[i]] = rA[i].w;
            *reinterpret_cast<float4*>(Bs + brow[i] * 128 + bc4[i] * 4) = rB[i];
        }
        __syncthreads();

        if (kt + BK < E_) {
#pragma unroll
            for (int i = 0; i < 2; i++) {
                rA[i] = *reinterpret_cast<const float4*>(apx[i] + kt + BK);
                rB[i] = *reinterpret_cast<const float4*>(bpx[i] + (size_t)(kt + BK) * G_);
            }
        }

#pragma unroll
        for (int k = 0; k < BK; k++) {
            float4 a0 = *reinterpret_cast<const float4*>(As + k * LDA + ty * 8);
            float4 a1 = *reinterpret_cast<const float4*>(As + k * LDA + ty * 8 + 4);
            u64 ad[8];
            ad[0] = pack2(a0.x, a0.x); ad[1] = pack2(a0.y, a0.y);
            ad[2] = pack2(a0.z, a0.z); ad[3] = pack2(a0.w, a0.w);
            ad[4] = pack2(a1.x, a1.x); ad[5] = pack2(a1.y, a1.y);
            ad[6] = pack2(a1.z, a1.z); ad[7] = pack2(a1.w, a1.w);
            const ulonglong2 q0 = *reinterpret_cast<const ulonglong2*>(Bs + k * 128 + tx * 4);
            const ulonglong2 q1 = *reinterpret_cast<const ulonglong2*>(Bs + k * 128 + 64 + tx * 4);
            u64 bp[4] = {q0.x, q0.y, q1.x, q1.y};
#pragma unroll
            for (int m = 0; m < 8; m++) {
                fma2(acc[m][0], ad[m], bp[0]);
                fma2(acc[m][1], ad[m], bp[1]);
                fma2(acc[m][2], ad[m], bp[2]);
                fma2(acc[m][3], ad[m], bp[3]);
            }
        }
        __syncthreads();
    }

    float* C = g_px + (size_t)dir * M_ * G_;
#pragma unroll
    for (int m = 0; m < 8; m++) {
        float* r = C + (size_t)(m0 + ty * 8 + m) * G_ + n0;
        ulonglong2 s0; s0.x = acc[m][0]; s0.y = acc[m][1];
        ulonglong2 s1; s1.x = acc[m][2]; s1.y = acc[m][3];
        *reinterpret_cast<ulonglong2*>(r + tx * 4)      = s0;
        *reinterpret_cast<ulonglong2*>(r + 64 + tx * 4) = s1;
    }
}

// ---------------------------------------------------------------------------
// Kernel 2: in-place LN3 over g_px. Warp-per-chunk. (proven)
// ---------------------------------------------------------------------------
__global__ __launch_bounds__(256) void ln3_kernel(
    const float* __restrict__ gf, const float* __restrict__ bf,
    const float* __restrict__ gb, const float* __restrict__ bb)
{
    const int w    = threadIdx.x >> 5;
    const int lane = threadIdx.x & 31;
    const int gidx = blockIdx.x * 8 + w;
    const int chunk = gidx % 3;
    const int row   = gidx / 3;
    const int dir   = row >> 15;
    const float* g  = (dir ? gb : gf) + chunk * 512;
    const float* be = (dir ? bb : bf) + chunk * 512;
    float* p = g_px + (size_t)row * G_ + chunk * 512;

    float4 v[4];
#pragma unroll
    for (int i = 0; i < 4; i++)
        v[i] = reinterpret_cast<float4*>(p)[lane + 32 * i];

    float s = 0.f, q = 0.f;
#pragma unroll
    for (int i = 0; i < 4; i++) {
        s += v[i].x + v[i].y + v[i].z + v[i].w;
        q += v[i].x * v[i].x + v[i].y * v[i].y + v[i].z * v[i].z + v[i].w * v[i].w;
    }
#pragma unroll
    for (int o = 16; o > 0; o >>= 1) {
        s += __shfl_xor_sync(0xffffffffu, s, o);
        q += __shfl_xor_sync(0xffffffffu, q, o);
    }
    const float mu = s * (1.f / 512.f);
    const float rs = rsqrtf(q * (1.f / 512.f) - mu * mu + LN_EPS);

#pragma unroll
    for (int i = 0; i < 4; i++) {
        float4 gv = reinterpret_cast<const float4*>(g)[lane + 32 * i];
        float4 bv = reinterpret_cast<const float4*>(be)[lane + 32 * i];
        float4 o;
        o.x = (v[i].x - mu) * rs * gv.x + bv.x;
        o.y = (v[i].y - mu) * rs * gv.y + bv.y;
        o.z = (v[i].z - mu) * rs * gv.z + bv.z;
        o.w = (v[i].w - mu) * rs * gv.w + bv.w;
        reinterpret_cast<float4*>(p)[lane + 32 * i] = o;
    }
}

// ---------------------------------------------------------------------------
// Kernel 3: persistent recurrence, 128 blocks (1/SM), 256 threads.
// G phase: 2 staged chunks of 256 k (was 4 x 128 k) -> fewer syncs/waits.
// ---------------------------------------------------------------------------
constexpr int SLICE = 24;

__device__ __forceinline__ void gridbar(int dir)
{
    __syncthreads();
    if (threadIdx.x == 0) {
        unsigned gen = *(volatile unsigned*)&g_gen2[dir];
        __threadfence();
        if (atomicAdd(&g_cnt2[dir], 1u) == 63u) {
            g_cnt2[dir] = 0u;
            __threadfence();
            *(volatile unsigned*)&g_gen2[dir] = gen + 1u;
        } else {
            while (*(volatile unsigned*)&g_gen2[dir] == gen) { __nanosleep(32); }
            __threadfence();
        }
    }
    __syncthreads();
}

// stage 256 k-rows (64 KB) of hT into smem
__device__ __forceinline__ void stage_chunk256(const float* gsrc, const float* dst, int t)
{
    unsigned saddr = (unsigned)__cvta_generic_to_shared(dst);
#pragma unroll
    for (int i = 0; i < 16; i++) {
        int off = (t + 256 * i) * 16;
        asm volatile("cp.async.cg.shared.global [%0], [%1], 16;"
                     :: "r"(saddr + off), "l"((const char*)gsrc + off) : "memory");
    }
    asm volatile("cp.async.commit_group;" ::: "memory");
}

__global__ __launch_bounds__(256) void rnn_kernel(
    const float* __restrict__ Whf, const float* __restrict__ Whb,
    const float* __restrict__ ghf, const float* __restrict__ bhf,
    const float* __restrict__ ghb, const float* __restrict__ bhb,
    const float* __restrict__ mask, float* __restrict__ out)
{
    extern __shared__ float smem[];
    float* sWh = smem;                    // [512][32] padded (j-groups of 8: 6 used)
    float* sh  = smem + 512 * 32;         // 2 x (256 k x 64 b) staging buffers
    __shared__ float sred[48];
    __shared__ float sstat[6];

    const int t   = threadIdx.x;
    const int blk = blockIdx.x;
    const int dir = blk >> 6;
    const int sub = blk & 63;             // G: j-slice id. U: batch row.
    const float* Wh = dir ? Whb : Whf;
    const float* gh = dir ? ghb : ghf;
    const float* bh = dir ? bhb : bhf;
    const int j0 = sub * SLICE;

    // G-phase thread decode: q = k-split (within chunk), jg = j-group, bg = b-group
    const int q  = t >> 6;
    const int jg = (t >> 4) & 3;
    const int bg = t & 15;
    const int pos = t & 63;

    // One-time: persistent Wh slice -> SMEM, padded [k][4][8]
    for (int i = t; i < 512 * SLICE; i += 256) {
        int k  = i / SLICE;
        int jj = i - k * SLICE;
        sWh[k * 32 + jj + (jj / 6) * 2] = Wh[(size_t)k * G_ + j0 + jj];
    }
    // One-time: zero this block's hT column range
    for (int i = t; i < 512; i += 256)
        g_hT[dir * 32768 + sub * 512 + i] = 0.f;

    // U-phase constants
    float gg6[6], bb6[6];
#pragma unroll
    for (int i = 0; i < 6; i++) {
        int j = (i >> 1) * 512 + (i & 1) * 256 + t;
        gg6[i] = gh[j];
        bb6[i] = bh[j];
    }
    const float* pxrow = g_px + ((size_t)(dir * 64 + sub)) * ((size_t)L_ * G_);
    const float* hTg = g_hT + dir * 32768;
    float* phd = g_ph + dir * 64 * G_;
    const float* mrow = mask + sub * 512;
    const int wj = t >> 5, lane = t & 31;

    float h0 = 0.f, h1 = 0.f;             // hidden state in registers (cols t, t+256)

    // software-pipelined U-phase inputs (prefetched one step ahead)
    float n_m, n_xz0, n_xr0, n_xg0, n_xz1, n_xr1, n_xg1;
    {
        const int t0 = dir ? 511 : 0;
        const float* npx = pxrow;        // s = 0
        n_m   = __ldg(mrow + t0);
        n_xz0 = __ldg(npx + t);        n_xz1 = __ldg(npx + 256 + t);
        n_xr0 = __ldg(npx + 512 + t);  n_xr1 = __ldg(npx + 768 + t);
        n_xg0 = __ldg(npx + 1024 + t); n_xg1 = __ldg(npx + 1280 + t);
    }

    gridbar(dir);                          // hT zeros visible

    for (int s = 0; s < L_; s++) {
        const int torig = dir ? (511 - s) : s;
        const float m = n_m;
        const float xz0 = n_xz0, xr0 = n_xr0, xg0 = n_xg0;
        const float xz1 = n_xz1, xr1 = n_xr1, xg1 = n_xg1;

        // ---- Phase G: ph[b][j0..j0+23] = sum_k hT[k][b] * Wh[k][j] ----
        u64 a[12];                         // [jp*4 + b] packed (j-even, j-odd)
#pragma unroll
        for (int i = 0; i < 12; i++) a[i] = 0ull;

        stage_chunk256(hTg,            sh,         t);   // k 0..255   -> buf0
        stage_chunk256(hTg + 256 * 64, sh + 16384, t);   // k 256..511 -> buf1

#pragma unroll
        for (int c = 0; c < 2; c++) {
            if (c == 0) asm volatile("cp.async.wait_group 1;" ::: "memory");
            else        asm volatile("cp.async.wait_group 0;" ::: "memory");
            __syncthreads();

            const float* wbase = sWh + (c * 256 + q * 64) * 32 + jg * 8;
            const float* hbase = sh + c * 16384 + (q * 64) * 64 + bg * 4;
#pragma unroll 8
            for (int kk = 0; kk < 64; kk++) {
                const ulonglong2 wp01 = *reinterpret_cast<const ulonglong2*>(wbase + kk * 32);
                const u64 wp2 = *reinterpret_cast<const u64*>(wbase + kk * 32 + 4);
                const float4 hv = *reinterpret_cast<const float4*>(hbase + kk * 64);
                u64 hd0 = pack2(hv.x, hv.x);
                u64 hd1 = pack2(hv.y, hv.y);
                u64 hd2 = pack2(hv.z, hv.z);
                u64 hd3 = pack2(hv.w, hv.w);
                fma2(a[0], wp01.x, hd0); fma2(a[1], wp01.x, hd1);
                fma2(a[2], wp01.x, hd2); fma2(a[3], wp01.x, hd3);
                fma2(a[4], wp01.y, hd0); fma2(a[5], wp01.y, hd1);
                fma2(a[6], wp01.y, hd2); fma2(a[7], wp01.y, hd3);
                fma2(a[8], wp2,    hd0); fma2(a[9], wp2,    hd1);
                fma2(a[10], wp2,   hd2); fma2(a[11], wp2,   hd3);
            }
        }

        // k-split reduction through buf0 (chunk0 reads all done: sync at c=1
        // ordered them; buf0 region is no longer read), then write ph
        {
            u64* red = reinterpret_cast<u64*>(sh);
            if (q) {
                u64* r = red + ((q - 1) * 64 + pos) * 12;
#pragma unroll
                for (int i = 0; i < 12; i++) r[i] = a[i];
            }
            __syncthreads();
            if (q == 0) {
#pragma unroll
                for (int w = 0; w < 3; w++) {
                    const u64* r = red + (w * 64 + pos) * 12;
#pragma unroll
                    for (int i = 0; i < 12; i++) a[i] = add2(a[i], r[i]);
                }
                const int jbase = j0 + jg * 6;
#pragma unroll
                for (int b = 0; b < 4; b++) {
                    u64* pr = reinterpret_cast<u64*>(phd + (size_t)(bg * 4 + b) * G_ + jbase);
                    pr[0] = a[b];
                    pr[1] = a[4 + b];
                    pr[2] = a[8 + b];
                }
            }
        }
        gridbar(dir);

        // ---- Phase U: LN3(ph) + GRU gates for batch row `sub` ----
        const float* phr = phd + (size_t)sub * G_;
        float v0 = __ldcg(phr + t);
        float v1 = __ldcg(phr + 256 + t);
        float v2 = __ldcg(phr + 512 + t);
        float v3 = __ldcg(phr + 768 + t);
        float v4 = __ldcg(phr + 1024 + t);
        float v5 = __ldcg(phr + 1280 + t);

        float p0 = v0 + v1, p1 = v2 + v3, p2 = v4 + v5;
        float q0 = v0 * v0 + v1 * v1;
        float q1 = v2 * v2 + v3 * v3;
        float q2 = v4 * v4 + v5 * v5;
#pragma unroll
        for (int o = 16; o > 0; o >>= 1) {
            p0 += __shfl_down_sync(0xffffffffu, p0, o);
            p1 += __shfl_down_sync(0xffffffffu, p1, o);
            p2 += __shfl_down_sync(0xffffffffu, p2, o);
            q0 += __shfl_down_sync(0xffffffffu, q0, o);
            q1 += __shfl_down_sync(0xffffffffu, q1, o);
            q2 += __shfl_down_sync(0xffffffffu, q2, o);
        }
        if (lane == 0) {
            sred[wj * 6 + 0] = p0; sred[wj * 6 + 1] = p1; sred[wj * 6 + 2] = p2;
            sred[wj * 6 + 3] = q0; sred[wj * 6 + 4] = q1; sred[wj * 6 + 5] = q2;
        }
        __syncthreads();
        if (t < 6) {
            float tot = 0.f;
#pragma unroll
            for (int w = 0; w < 8; w++) tot += sred[w * 6 + t];
            sstat[t] = tot;
        }
        __syncthreads();
        const float mu0 = sstat[0] * (1.f / 512.f);
        const float mu1 = sstat[1] * (1.f / 512.f);
        const float mu2 = sstat[2] * (1.f / 512.f);
        const float rs0 = rsqrtf(sstat[3] * (1.f / 512.f) - mu0 * mu0 + LN_EPS);
        const float rs1 = rsqrtf(sstat[4] * (1.f / 512.f) - mu1 * mu1 + LN_EPS);
        const float rs2 = rsqrtf(sstat[5] * (1.f / 512.f) - mu2 * mu2 + LN_EPS);

        float* outt = out + ((size_t)sub * 512 + torig) * 1024 + dir * 512;
        float* hwr = g_hT + dir * 32768;

        float o0, o1;
        // half 0: column t
        {
            float phz  = (v0 - mu0) * rs0 * gg6[0] + bb6[0];
            float phrv = (v2 - mu1) * rs1 * gg6[2] + bb6[2];
            float phgv = (v4 - mu2) * rs2 * gg6[4] + bb6[4];
            float z  = sig_fast(xz0 + phz);
            float r  = sig_fast(xr0 + phrv);
            float gv = tanh_fast(xg0 + r * phgv);
            h0 = h0 + m * z * (gv - h0);
            hwr[t * 64 + sub] = h0;
            o0 = h0 * m;
        }
        // half 1: column t+256
        {
            float phz  = (v1 - mu0) * rs0 * gg6[1] + bb6[1];
            float phrv = (v3 - mu1) * rs1 * gg6[3] + bb6[3];
            float phgv = (v5 - mu2) * rs2 * gg6[5] + bb6[5];
            float z  = sig_fast(xz1 + phz);
            float r  = sig_fast(xr1 + phrv);
            float gv = tanh_fast(xg1 + r * phgv);
            h1 = h1 + m * z * (gv - h1);
            hwr[(t + 256) * 64 + sub] = h1;
            o1 = h1 * m;
        }

        // ---- bar2: arrive early; overlap out-stores + next-step prefetch ----
        __syncthreads();                    // hT stores complete block-wide
        unsigned genl = 0;
        bool released = false;
        if (t == 0) {
            genl = *(volatile unsigned*)&g_gen2[dir];
            __threadfence();                // publish hT
            if (atomicAdd(&g_cnt2[dir], 1u) == 63u) {
                g_cnt2[dir] = 0u;
                __threadfence();
                *(volatile unsigned*)&g_gen2[dir] = genl + 1u;
                released = true;
            }
        }
        // overlapped work (not ordered by the barrier):
        outt[t]       = o0;
        outt[t + 256] = o1;
        if (s + 1 < L_) {
            const int nto = dir ? (510 - s) : (s + 1);
            const float* npx = pxrow + (size_t)(s + 1) * G_;
            n_m   = __ldg(mrow + nto);
            n_xz0 = __ldg(npx + t);        n_xz1 = __ldg(npx + 256 + t);
            n_xr0 = __ldg(npx + 512 + t);  n_xr1 = __ldg(npx + 768 + t);
            n_xg0 = __ldg(npx + 1024 + t); n_xg1 = __ldg(npx + 1280 + t);
        }
        if (t == 0 && !released) {
            while (*(volatile unsigned*)&g_gen2[dir] == genl) { __nanosleep(32); }
            __threadfence();
        }
        __syncthreads();
    }
}

// ---------------------------------------------------------------------------
extern "C" void kernel_launch(void* const* d_in, const int* in_sizes, int n_in,
                              void* d_out, int out_size)
{
    const float* xs    = (const float*)d_in[0];
    const float* xmask = (const float*)d_in[1];
    const float* fWx   = (const float*)d_in[2];
    const float* fWh   = (const float*)d_in[3];
    const float* fgx   = (const float*)d_in[4];
    const float* fbx   = (const float*)d_in[5];
    const float* fgh   = (const float*)d_in[6];
    const float* fbh   = (const float*)d_in[7];
    const float* bWx   = (const float*)d_in[8];
    const float* bWh   = (const float*)d_in[9];
    const float* bgx   = (const float*)d_in[10];
    const float* bbx   = (const float*)d_in[11];
    const float* bgh   = (const float*)d_in[12];
    const float* bbh   = (const float*)d_in[13];
    float* out = (float*)d_out;

    // dynamic smem: Wh slice (64KB) + 2 x 64KB staging buffers = 192KB
    const int rnn_smem = (512 * 32 + 2 * 256 * 64) * (int)sizeof(float);  // 196608
    cudaFuncSetAttribute(rnn_kernel, cudaFuncAttributeMaxDynamicSharedMemorySize, rnn_smem);

    // 1) px = xs @ Wx (both directions; dir=1 uses time-reversed xs)
    dim3 ggrid(G_ / 128, M_ / 128, 2);
    gemm_px_kernel<<<ggrid, 256>>>(xs, fWx, bWx);

    // 2) in-place LN3 on px (warp-per-chunk)
    ln3_kernel<<<2 * M_ * 3 / 8, 256>>>(fgx, fbx, bgx, bbx);

    // 3) persistent bidirectional GRU recurrence
    rnn_kernel<<<128, 256, rnn_smem>>>(fWh, bWh, fgh, fbh, bgh, bbh, xmask, out);
}

// round 16
// speedup vs baseline: 1.1393x; 1.1393x over previous
#include <cuda_runtime.h>
#include <cuda_bf16.h>
#include <cstdint>
#include <cstddef>

using u64 = unsigned long long;

// Problem constants
constexpr int B_ = 64;
constexpr int L_ = 512;
constexpr int E_ = 512;
constexpr int G_ = 1536;          // 3*H
constexpr int M_ = B_ * L_;       // 32768 rows per direction
constexpr float LN_EPS = 1e-5f;

// Scratch (device globals: allocation-free)
__device__ float g_px[2ull * 32768ull * 1536ull];   // LN3(x @ Wx) per dir
__device__ float g_ph[2 * 64 * 1536];               // per-step h @ Wh
__device__ float g_hT[2 * 512 * 64];                // hidden transposed [dir][k][b]
__device__ unsigned g_cnt2[2];                      // per-dir grid barrier
__device__ unsigned g_gen2[2];
__device__ __nv_bfloat16 g_A[32768ull * 1536ull];   // [m][hi|lo|hi] split-bf16 xs
__device__ __nv_bfloat16 g_B[2ull * 1536ull * 1536ull]; // [dir][n][hi|hi|lo] Wx^T

// ---------------- packed f32x2 / fast-math helpers ----------------
__device__ __forceinline__ u64 pack2(float x, float y) {
    u64 r; asm("mov.b64 %0,{%1,%2};" : "=l"(r) : "f"(x), "f"(y)); return r;
}
__device__ __forceinline__ void fma2(u64& d, u64 a, u64 b) {
    asm("fma.rn.f32x2 %0,%1,%2,%0;" : "+l"(d) : "l"(a), "l"(b));
}
__device__ __forceinline__ u64 add2(u64 a, u64 b) {
    u64 d; asm("add.rn.f32x2 %0,%1,%2;" : "=l"(d) : "l"(a), "l"(b)); return d;
}
__device__ __forceinline__ float tanh_fast(float x) {
    float y; asm("tanh.approx.f32 %0,%1;" : "=f"(y) : "f"(x)); return y;
}
__device__ __forceinline__ float sig_fast(float x) {
    return 0.5f + 0.5f * tanh_fast(0.5f * x);
}
__device__ __forceinline__ uint32_t smem_u32(const void* p) {
    uint32_t a;
    asm("{ .reg .u64 tmp; cvta.to.shared.u64 tmp, %1; cvt.u32.u64 %0, tmp; }"
        : "=r"(a) : "l"(p));
    return a;
}
__device__ __forceinline__ void ldm_x4(uint32_t* r, uint32_t addr) {
    asm volatile("ldmatrix.sync.aligned.m8n8.x4.shared.b16 {%0,%1,%2,%3}, [%4];"
        : "=r"(r[0]), "=r"(r[1]), "=r"(r[2]), "=r"(r[3]) : "r"(addr));
}
__device__ __forceinline__ void mma16816(float* c, const uint32_t* a,
                                         uint32_t b0, uint32_t b1) {
    asm volatile(
        "mma.sync.aligned.m16n8k16.row.col.f32.bf16.bf16.f32 "
        "{%0,%1,%2,%3}, {%4,%5,%6,%7}, {%8,%9}, {%0,%1,%2,%3};"
        : "+f"(c[0]), "+f"(c[1]), "+f"(c[2]), "+f"(c[3])
        : "r"(a[0]), "r"(a[1]), "r"(a[2]), "r"(a[3]), "r"(b0), "r"(b1));
}

// ---------------------------------------------------------------------------
// Prep 1: split xs into bf16 hi/lo:  A'[m] = [hi(0..511) | lo | hi]
// ---------------------------------------------------------------------------
__global__ __launch_bounds__(128) void conv_a_kernel(const float* __restrict__ xs)
{
    const int m = blockIdx.x;
    const float* src = xs + (size_t)m * 512;
    __nv_bfloat16* dst = g_A + (size_t)m * 1536;
    const int k = threadIdx.x * 4;
    float4 v = *reinterpret_cast<const float4*>(src + k);
    float f[4] = {v.x, v.y, v.z, v.w};
    __nv_bfloat16 hi[4], lo[4];
#pragma unroll
    for (int i = 0; i < 4; i++) {
        hi[i] = __float2bfloat16(f[i]);
        lo[i] = __float2bfloat16(f[i] - __bfloat162float(hi[i]));
    }
    __nv_bfloat162 h01, h23, l01, l23;
    h01.x = hi[0]; h01.y = hi[1]; h23.x = hi[2]; h23.y = hi[3];
    l01.x = lo[0]; l01.y = lo[1]; l23.x = lo[2]; l23.y = lo[3];
    *reinterpret_cast<__nv_bfloat162*>(dst + k)           = h01;
    *reinterpret_cast<__nv_bfloat162*>(dst + k + 2)       = h23;
    *reinterpret_cast<__nv_bfloat162*>(dst + 512 + k)     = l01;
    *reinterpret_cast<__nv_bfloat162*>(dst + 512 + k + 2) = l23;
    *reinterpret_cast<__nv_bfloat162*>(dst + 1024 + k)    = h01;
    *reinterpret_cast<__nv_bfloat162*>(dst + 1024 + k + 2)= h23;
}

// ---------------------------------------------------------------------------
// Prep 2: B'[dir][n] = [hi(Wx[:,n]) | hi | lo]   (Wx is [E][G] row-major)
// ---------------------------------------------------------------------------
__global__ __launch_bounds__(128) void conv_b_kernel(
    const float* __restrict__ Wxf, const float* __restrict__ Wxb)
{
    const int n   = blockIdx.x;
    const int dir = blockIdx.y;
    const float* W = dir ? Wxb : Wxf;
    __nv_bfloat16* dst = g_B + (size_t)dir * 1536 * 1536 + (size_t)n * 1536;
#pragma unroll
    for (int j = 0; j < 4; j++) {
        int k = threadIdx.x + j * 128;
        float w = W[(size_t)k * G_ + n];
        __nv_bfloat16 h = __float2bfloat16(w);
        __nv_bfloat16 l = __float2bfloat16(w - __bfloat162float(h));
        dst[k] = h; dst[512 + k] = h; dst[1024 + k] = l;
    }
}

// ---------------------------------------------------------------------------
// Kernel 1: px = A' @ B'^T via mma.sync bf16 (HMMA).  Tile 128x128, K'=1536,
// BK=32 double-buffered cp.async, 8 warps (64x32 warp tiles), ldmatrix frags.
// ---------------------------------------------------------------------------
constexpr int LDT = 40;                 // smem row stride in bf16 (80 bytes)

__global__ __launch_bounds__(256, 2) void gemm_px_mma()
{
    __shared__ __align__(16) __nv_bfloat16 Abuf[2][128 * LDT];
    __shared__ __align__(16) __nv_bfloat16 Bbuf[2][128 * LDT];

    const int t    = threadIdx.x;
    const int lane = t & 31;
    const int wid  = t >> 5;
    const int dir  = blockIdx.z;
    const int m0   = blockIdx.y * 128;
    const int n0   = blockIdx.x * 128;
    const int warp_m = (wid >> 2) * 64;
    const int warp_n = (wid & 3) * 32;

    const uint32_t aS = smem_u32(&Abuf[0][0]);
    const uint32_t bS = smem_u32(&Bbuf[0][0]);
    const uint32_t STG = 128 * LDT * 2;     // stage stride in bytes (10240)

    // cp.async addressing: 2 A-chunks + 2 B-chunks of 16B per thread per tile
    const __nv_bfloat16* asrc[2];
    const __nv_bfloat16* bsrc[2];
    uint32_t cdst[2];
#pragma unroll
    for (int i = 0; i < 2; i++) {
        int idx = t + 256 * i;              // 0..511
        int r = idx >> 2, ch = idx & 3;
        cdst[i] = (uint32_t)(r * LDT * 2 + ch * 16);
        int m = m0 + r, b = m >> 9, s = m & 511;
        int torig = dir ? (511 - s) : s;
        asrc[i] = g_A + (size_t)(b * 512 + torig) * 1536 + ch * 8;
        bsrc[i] = g_B + (size_t)dir * 1536 * 1536 + (size_t)(n0 + r) * 1536 + ch * 8;
    }

    auto load_tile = [&](int kt) {
        int st = kt & 1;
        uint32_t ab = aS + st * STG, bb = bS + st * STG;
#pragma unroll
        for (int i = 0; i < 2; i++) {
            asm volatile("cp.async.cg.shared.global [%0], [%1], 16;"
                         :: "r"(ab + cdst[i]), "l"(asrc[i] + kt * 32) : "memory");
            asm volatile("cp.async.cg.shared.global [%0], [%1], 16;"
                         :: "r"(bb + cdst[i]), "l"(bsrc[i] + kt * 32) : "memory");
        }
        asm volatile("cp.async.commit_group;" ::: "memory");
    };

    // ldmatrix per-lane base offsets (bytes)
    const uint32_t a_off =
        (uint32_t)(((warp_m + (lane & 15)) * LDT + (lane >> 4) * 8) * 2);
    const uint32_t b_off =
        (uint32_t)(((warp_n + (lane & 7) + ((lane >> 4) << 3)) * LDT
                    + ((lane >> 3) & 1) * 8) * 2);

    float acc[4][4][4];
#pragma unroll
    for (int mi = 0; mi < 4; mi++)
#pragma unroll
        for (int nj = 0; nj < 4; nj++)
#pragma unroll
            for (int e = 0; e < 4; e++) acc[mi][nj][e] = 0.f;

    load_tile(0);
    load_tile(1);

    for (int kt = 0; kt < 48; kt++) {
        if (kt < 47) asm volatile("cp.async.wait_group 1;" ::: "memory");
        else         asm volatile("cp.async.wait_group 0;" ::: "memory");
        __syncthreads();

        const uint32_t ab = aS + (kt & 1) * STG;
        const uint32_t bb = bS + (kt & 1) * STG;
#pragma unroll
        for (int ks = 0; ks < 2; ks++) {
            uint32_t af[4][4], bf[2][4];
#pragma unroll
            for (int mi = 0; mi < 4; mi++)
                ldm_x4(af[mi], ab + a_off + (uint32_t)((mi * 16 * LDT + ks * 16) * 2));
#pragma unroll
            for (int p = 0; p < 2; p++)
                ldm_x4(bf[p], bb + b_off + (uint32_t)((p * 16 * LDT + ks * 16) * 2));
#pragma unroll
            for (int mi = 0; mi < 4; mi++)
#pragma unroll
                for (int nj = 0; nj < 4; nj++)
                    mma16816(acc[mi][nj], af[mi],
                             bf[nj >> 1][(nj & 1) * 2], bf[nj >> 1][(nj & 1) * 2 + 1]);
        }
        __syncthreads();
        if (kt + 2 < 48) load_tile(kt + 2);
    }

    // Epilogue: standard m16n8 fragment layout -> float2 stores
    float* C = g_px + (size_t)dir * M_ * G_;
    const int r0 = m0 + warp_m + (lane >> 2);
    const int c0 = n0 + warp_n + (lane & 3) * 2;
#pragma unroll
    for (int mi = 0; mi < 4; mi++) {
#pragma unroll
        for (int nj = 0; nj < 4; nj++) {
            float* p0 = C + (size_t)(r0 + mi * 16) * G_ + c0 + nj * 8;
            float2 lo; lo.x = acc[mi][nj][0]; lo.y = acc[mi][nj][1];
            float2 hi; hi.x = acc[mi][nj][2]; hi.y = acc[mi][nj][3];
            *reinterpret_cast<float2*>(p0)          = lo;
            *reinterpret_cast<float2*>(p0 + 8 * G_) = hi;
        }
    }
}

// ---------------------------------------------------------------------------
// Kernel 2: in-place LN3 over g_px. Warp-per-chunk. (proven R12)
// ---------------------------------------------------------------------------
__global__ __launch_bounds__(256) void ln3_kernel(
    const float* __restrict__ gf, const float* __restrict__ bf,
    const float* __restrict__ gb, const float* __restrict__ bb)
{
    const int w    = threadIdx.x >> 5;
    const int lane = threadIdx.x & 31;
    const int gidx = blockIdx.x * 8 + w;
    const int chunk = gidx % 3;
    const int row   = gidx / 3;
    const int dir   = row >> 15;
    const float* g  = (dir ? gb : gf) + chunk * 512;
    const float* be = (dir ? bb : bf) + chunk * 512;
    float* p = g_px + (size_t)row * G_ + chunk * 512;

    float4 v[4];
#pragma unroll
    for (int i = 0; i < 4; i++)
        v[i] = reinterpret_cast<float4*>(p)[lane + 32 * i];

    float s = 0.f, q = 0.f;
#pragma unroll
    for (int i = 0; i < 4; i++) {
        s += v[i].x + v[i].y + v[i].z + v[i].w;
        q += v[i].x * v[i].x + v[i].y * v[i].y + v[i].z * v[i].z + v[i].w * v[i].w;
    }
#pragma unroll
    for (int o = 16; o > 0; o >>= 1) {
        s += __shfl_xor_sync(0xffffffffu, s, o);
        q += __shfl_xor_sync(0xffffffffu, q, o);
    }
    const float mu = s * (1.f / 512.f);
    const float rs = rsqrtf(q * (1.f / 512.f) - mu * mu + LN_EPS);

#pragma unroll
    for (int i = 0; i < 4; i++) {
        float4 gv = reinterpret_cast<const float4*>(g)[lane + 32 * i];
        float4 bv = reinterpret_cast<const float4*>(be)[lane + 32 * i];
        float4 o;
        o.x = (v[i].x - mu) * rs * gv.x + bv.x;
        o.y = (v[i].y - mu) * rs * gv.y + bv.y;
        o.z = (v[i].z - mu) * rs * gv.z + bv.z;
        o.w = (v[i].w - mu) * rs * gv.w + bv.w;
        reinterpret_cast<float4*>(p)[lane + 32 * i] = o;
    }
}

// ---------------------------------------------------------------------------
// Kernel 3: persistent recurrence — EXACT R12 configuration (proven 8018us).
// ---------------------------------------------------------------------------
constexpr int SLICE = 24;

__device__ __forceinline__ void gridbar(int dir)
{
    __syncthreads();
    if (threadIdx.x == 0) {
        unsigned gen = *(volatile unsigned*)&g_gen2[dir];
        __threadfence();
        if (atomicAdd(&g_cnt2[dir], 1u) == 63u) {
            g_cnt2[dir] = 0u;
            __threadfence();
            *(volatile unsigned*)&g_gen2[dir] = gen + 1u;
        } else {
            while (*(volatile unsigned*)&g_gen2[dir] == gen) { __nanosleep(32); }
            __threadfence();
        }
    }
    __syncthreads();
}

__device__ __forceinline__ void stage_chunk(const float* gsrc, const float* dst, int t)
{
    unsigned saddr = (unsigned)__cvta_generic_to_shared(dst);
#pragma unroll
    for (int i = 0; i < 8; i++) {
        int off = (t + 256 * i) * 16;
        asm volatile("cp.async.cg.shared.global [%0], [%1], 16;"
                     :: "r"(saddr + off), "l"((const char*)gsrc + off) : "memory");
    }
    asm volatile("cp.async.commit_group;" ::: "memory");
}

__global__ __launch_bounds__(256) void rnn_kernel(
    const float* __restrict__ Whf, const float* __restrict__ Whb,
    const float* __restrict__ ghf, const float* __restrict__ bhf,
    const float* __restrict__ ghb, const float* __restrict__ bhb,
    const float* __restrict__ mask, float* __restrict__ out)
{
    extern __shared__ float smemf[];
    float* sWh = smemf;                   // [512][32] padded (j-groups of 8: 6 used)
    float* sh  = smemf + 512 * 32;        // 2 x (128 k x 64 b) staging buffers
    __shared__ float sred[48];
    __shared__ float sstat[6];

    const int t   = threadIdx.x;
    const int blk = blockIdx.x;
    const int dir = blk >> 6;
    const int sub = blk & 63;             // G: j-slice id. U: batch row.
    const float* Wh = dir ? Whb : Whf;
    const float* gh = dir ? ghb : ghf;
    const float* bh = dir ? bhb : bhf;
    const int j0 = sub * SLICE;

    const int q  = t >> 6;
    const int jg = (t >> 4) & 3;
    const int bg = t & 15;
    const int pos = t & 63;

    for (int i = t; i < 512 * SLICE; i += 256) {
        int k  = i / SLICE;
        int jj = i - k * SLICE;
        sWh[k * 32 + jj + (jj / 6) * 2] = Wh[(size_t)k * G_ + j0 + jj];
    }
    for (int i = t; i < 512; i += 256)
        g_hT[dir * 32768 + sub * 512 + i] = 0.f;

    float gg6[6], bb6[6];
#pragma unroll
    for (int i = 0; i < 6; i++) {
        int j = (i >> 1) * 512 + (i & 1) * 256 + t;
        gg6[i] = gh[j];
        bb6[i] = bh[j];
    }
    const float* pxrow = g_px + ((size_t)(dir * 64 + sub)) * ((size_t)L_ * G_);
    const float* hTg = g_hT + dir * 32768;
    float* phd = g_ph + dir * 64 * G_;
    const float* mrow = mask + sub * 512;
    const int wj = t >> 5, lane = t & 31;

    float h0 = 0.f, h1 = 0.f;

    float n_m, n_xz0, n_xr0, n_xg0, n_xz1, n_xr1, n_xg1;
    {
        const int t0 = dir ? 511 : 0;
        const float* npx = pxrow;
        n_m   = __ldg(mrow + t0);
        n_xz0 = __ldg(npx + t);        n_xz1 = __ldg(npx + 256 + t);
        n_xr0 = __ldg(npx + 512 + t);  n_xr1 = __ldg(npx + 768 + t);
        n_xg0 = __ldg(npx + 1024 + t); n_xg1 = __ldg(npx + 1280 + t);
    }

    gridbar(dir);

    for (int s = 0; s < L_; s++) {
        const int torig = dir ? (511 - s) : s;
        const float m = n_m;
        const float xz0 = n_xz0, xr0 = n_xr0, xg0 = n_xg0;
        const float xz1 = n_xz1, xr1 = n_xr1, xg1 = n_xg1;

        u64 a[12];
#pragma unroll
        for (int i = 0; i < 12; i++) a[i] = 0ull;

        stage_chunk(hTg,            sh,        t);
        stage_chunk(hTg + 128 * 64, sh + 8192, t);

        for (int c = 0; c < 4; c++) {
            if (c == 3) asm volatile("cp.async.wait_group 0;" ::: "memory");
            else        asm volatile("cp.async.wait_group 1;" ::: "memory");
            __syncthreads();

            const float* shc   = sh + (c & 1) * 8192;
            const float* wbase = sWh + (c * 128 + q * 32) * 32 + jg * 8;
            const float* hbase = shc + (q * 32) * 64 + bg * 4;
#pragma unroll 8
            for (int kk = 0; kk < 32; kk++) {
                const ulonglong2 wp01 = *reinterpret_cast<const ulonglong2*>(wbase + kk * 32);
                const u64 wp2 = *reinterpret_cast<const u64*>(wbase + kk * 32 + 4);
                const float4 hv = *reinterpret_cast<const float4*>(hbase + kk * 64);
                u64 hd0 = pack2(hv.x, hv.x);
                u64 hd1 = pack2(hv.y, hv.y);
                u64 hd2 = pack2(hv.z, hv.z);
                u64 hd3 = pack2(hv.w, hv.w);
                fma2(a[0], wp01.x, hd0); fma2(a[1], wp01.x, hd1);
                fma2(a[2], wp01.x, hd2); fma2(a[3], wp01.x, hd3);
                fma2(a[4], wp01.y, hd0); fma2(a[5], wp01.y, hd1);
                fma2(a[6], wp01.y, hd2); fma2(a[7], wp01.y, hd3);
                fma2(a[8], wp2,    hd0); fma2(a[9], wp2,    hd1);
                fma2(a[10], wp2,   hd2); fma2(a[11], wp2,   hd3);
            }
            __syncthreads();
            if (c < 2)
                stage_chunk(hTg + (c + 2) * 128 * 64, sh + (c & 1) * 8192, t);
        }

        {
            u64* red = reinterpret_cast<u64*>(sh);
            if (q) {
                u64* r = red + ((q - 1) * 64 + pos) * 12;
#pragma unroll
                for (int i = 0; i < 12; i++) r[i] = a[i];
            }
            __syncthreads();
            if (q == 0) {
#pragma unroll
                for (int w = 0; w < 3; w++) {
                    const u64* r = red + (w * 64 + pos) * 12;
#pragma unroll
                    for (int i = 0; i < 12; i++) a[i] = add2(a[i], r[i]);
                }
                const int jbase = j0 + jg * 6;
#pragma unroll
                for (int b = 0; b < 4; b++) {
                    u64* pr = reinterpret_cast<u64*>(phd + (size_t)(bg * 4 + b) * G_ + jbase);
                    pr[0] = a[b];
                    pr[1] = a[4 + b];
                    pr[2] = a[8 + b];
                }
            }
        }
        gridbar(dir);

        const float* phr = phd + (size_t)sub * G_;
        float v0 = __ldcg(phr + t);
        float v1 = __ldcg(phr + 256 + t);
        float v2 = __ldcg(phr + 512 + t);
        float v3 = __ldcg(phr + 768 + t);
        float v4 = __ldcg(phr + 1024 + t);
        float v5 = __ldcg(phr + 1280 + t);

        float p0 = v0 + v1, p1 = v2 + v3, p2 = v4 + v5;
        float q0 = v0 * v0 + v1 * v1;
        float q1 = v2 * v2 + v3 * v3;
        float q2 = v4 * v4 + v5 * v5;
#pragma unroll
        for (int o = 16; o > 0; o >>= 1) {
            p0 += __shfl_down_sync(0xffffffffu, p0, o);
            p1 += __shfl_down_sync(0xffffffffu, p1, o);
            p2 += __shfl_down_sync(0xffffffffu, p2, o);
            q0 += __shfl_down_sync(0xffffffffu, q0, o);
            q1 += __shfl_down_sync(0xffffffffu, q1, o);
            q2 += __shfl_down_sync(0xffffffffu, q2, o);
        }
        if (lane == 0) {
            sred[wj * 6 + 0] = p0; sred[wj * 6 + 1] = p1; sred[wj * 6 + 2] = p2;
            sred[wj * 6 + 3] = q0; sred[wj * 6 + 4] = q1; sred[wj * 6 + 5] = q2;
        }
        __syncthreads();
        if (t < 6) {
            float tot = 0.f;
#pragma unroll
            for (int w = 0; w < 8; w++) tot += sred[w * 6 + t];
            sstat[t] = tot;
        }
        __syncthreads();
        const float mu0 = sstat[0] * (1.f / 512.f);
        const float mu1 = sstat[1] * (1.f / 512.f);
        const float mu2 = sstat[2] * (1.f / 512.f);
        const float rs0 = rsqrtf(sstat[3] * (1.f / 512.f) - mu0 * mu0 + LN_EPS);
        const float rs1 = rsqrtf(sstat[4] * (1.f / 512.f) - mu1 * mu1 + LN_EPS);
        const float rs2 = rsqrtf(sstat[5] * (1.f / 512.f) - mu2 * mu2 + LN_EPS);

        float* outt = out + ((size_t)sub * 512 + torig) * 1024 + dir * 512;
        float* hwr = g_hT + dir * 32768;

        float o0, o1;
        {
            float phz  = (v0 - mu0) * rs0 * gg6[0] + bb6[0];
            float phrv = (v2 - mu1) * rs1 * gg6[2] + bb6[2];
            float phgv = (v4 - mu2) * rs2 * gg6[4] + bb6[4];
            float z  = sig_fast(xz0 + phz);
            float r  = sig_fast(xr0 + phrv);
            float gv = tanh_fast(xg0 + r * phgv);
            h0 = h0 + m * z * (gv - h0);
            hwr[t * 64 + sub] = h0;
            o0 = h0 * m;
        }
        {
            float phz  = (v1 - mu0) * rs0 * gg6[1] + bb6[1];
            float phrv = (v3 - mu1) * rs1 * gg6[3] + bb6[3];
            float phgv = (v5 - mu2) * rs2 * gg6[5] + bb6[5];
            float z  = sig_fast(xz1 + phz);
            float r  = sig_fast(xr1 + phrv);
            float gv = tanh_fast(xg1 + r * phgv);
            h1 = h1 + m * z * (gv - h1);
            hwr[(t + 256) * 64 + sub] = h1;
            o1 = h1 * m;
        }

        __syncthreads();
        unsigned genl = 0;
        bool released = false;
        if (t == 0) {
            genl = *(volatile unsigned*)&g_gen2[dir];
            __threadfence();
            if (atomicAdd(&g_cnt2[dir], 1u) == 63u) {
                g_cnt2[dir] = 0u;
                __threadfence();
                *(volatile unsigned*)&g_gen2[dir] = genl + 1u;
                released = true;
            }
        }
        outt[t]       = o0;
        outt[t + 256] = o1;
        if (s + 1 < L_) {
            const int nto = dir ? (510 - s) : (s + 1);
            const float* npx = pxrow + (size_t)(s + 1) * G_;
            n_m   = __ldg(mrow + nto);
            n_xz0 = __ldg(npx + t);        n_xz1 = __ldg(npx + 256 + t);
            n_xr0 = __ldg(npx + 512 + t);  n_xr1 = __ldg(npx + 768 + t);
            n_xg0 = __ldg(npx + 1024 + t); n_xg1 = __ldg(npx + 1280 + t);
        }
        if (t == 0 && !released) {
            while (*(volatile unsigned*)&g_gen2[dir] == genl) { __nanosleep(32); }
            __threadfence();
        }
        __syncthreads();
    }
}

// ---------------------------------------------------------------------------
extern "C" void kernel_launch(void* const* d_in, const int* in_sizes, int n_in,
                              void* d_out, int out_size)
{
    const float* xs    = (const float*)d_in[0];
    const float* xmask = (const float*)d_in[1];
    const float* fWx   = (const float*)d_in[2];
    const float* fWh   = (const float*)d_in[3];
    const float* fgx   = (const float*)d_in[4];
    const float* fbx   = (const float*)d_in[5];
    const float* fgh   = (const float*)d_in[6];
    const float* fbh   = (const float*)d_in[7];
    const float* bWx   = (const float*)d_in[8];
    const float* bWh   = (const float*)d_in[9];
    const float* bgx   = (const float*)d_in[10];
    const float* bbx   = (const float*)d_in[11];
    const float* bgh   = (const float*)d_in[12];
    const float* bbh   = (const float*)d_in[13];
    float* out = (float*)d_out;

    const int rnn_smem = (512 * 32 + 2 * 128 * 64) * (int)sizeof(float);  // 131072
    cudaFuncSetAttribute(rnn_kernel, cudaFuncAttributeMaxDynamicSharedMemorySize, rnn_smem);

    // 1) split-bf16 prep
    conv_a_kernel<<<32768, 128>>>(xs);
    conv_b_kernel<<<dim3(1536, 2), 128>>>(fWx, bWx);

    // 2) px = A' @ B'^T on tensor cores (mma.sync bf16, split compensation)
    gemm_px_mma<<<dim3(12, 256, 2), 256>>>();

    // 3) in-place LN3 on px (warp-per-chunk)
    ln3_kernel<<<2 * M_ * 3 / 8, 256>>>(fgx, fbx, bgx, bbx);

    // 4) persistent bidirectional GRU recurrence (proven R12 config)
    rnn_kernel<<<128, 256, rnn_smem>>>(fWh, bWh, fgh, fbh, bgh, bbh, xmask, out);
}